// round 8
// baseline (speedup 1.0000x reference)
#include <cuda_runtime.h>
#include <cuda_fp16.h>
#include <cstdint>

// out = x @ kernel[2]  (seq_len==1 -> softmax over length-1 axis is identity)
// x: [8192,1024] f32, kernel: [3,1024,1024] f32, out: [8192,1024] f32
#define BROWS 8192
#define DDIM  1024

__device__ __half g_xh[BROWS * DDIM];   // 16 MB
__device__ __half g_wh[DDIM * DDIM];    // 2 MB, [K,N] row-major

// ------------------------- PTX helpers -------------------------
static __device__ __forceinline__ uint32_t smem_u32(const void* p) {
    uint32_t a;
    asm("{ .reg .u64 t; cvta.to.shared.u64 t, %1; cvt.u32.u64 %0, t; }" : "=r"(a) : "l"(p));
    return a;
}
static __device__ __forceinline__ void cpa16(uint32_t saddr, const void* gptr) {
    asm volatile("cp.async.cg.shared.global [%0], [%1], 16;" :: "r"(saddr), "l"(gptr));
}
static __device__ __forceinline__ void cp_commit() {
    asm volatile("cp.async.commit_group;" ::: "memory");
}
static __device__ __forceinline__ void cp_wait2() {
    asm volatile("cp.async.wait_group 2;" ::: "memory");
}
static __device__ __forceinline__ void cp_wait1() {
    asm volatile("cp.async.wait_group 1;" ::: "memory");
}
static __device__ __forceinline__ void cp_wait0() {
    asm volatile("cp.async.wait_group 0;" ::: "memory");
}
static __device__ __forceinline__ void ldsm4(uint32_t* r, uint32_t a) {
    asm volatile("ldmatrix.sync.aligned.m8n8.x4.shared.b16 {%0,%1,%2,%3}, [%4];"
                 : "=r"(r[0]), "=r"(r[1]), "=r"(r[2]), "=r"(r[3]) : "r"(a));
}
static __device__ __forceinline__ void ldsm4t(uint32_t* r, uint32_t a) {
    asm volatile("ldmatrix.sync.aligned.m8n8.x4.trans.shared.b16 {%0,%1,%2,%3}, [%4];"
                 : "=r"(r[0]), "=r"(r[1]), "=r"(r[2]), "=r"(r[3]) : "r"(a));
}
// f16-accumulator MMA: D,C are 2 regs (f16x2 pairs)
static __device__ __forceinline__ void mma16816_f16(uint32_t* c, const uint32_t* a,
                                                    const uint32_t* b) {
    asm volatile(
        "mma.sync.aligned.m16n8k16.row.col.f16.f16.f16.f16 "
        "{%0,%1}, {%2,%3,%4,%5}, {%6,%7}, {%0,%1};"
        : "+r"(c[0]), "+r"(c[1])
        : "r"(a[0]), "r"(a[1]), "r"(a[2]), "r"(a[3]), "r"(b[0]), "r"(b[1]));
}

// ------------------------- convert kernel -------------------------
// Blocks 0..2047 convert x, 2048..2303 convert w (nx4 = 2048*1024, exact split).
__global__ void __launch_bounds__(256) cvt_kernel(const float4* __restrict__ x,
                                                  const float4* __restrict__ w,
                                                  int nx4) {
    int base = blockIdx.x * 1024 + threadIdx.x;
    const float4* src;
    uint2* dst;
    if (base < nx4) {
        src = x;
        dst = (uint2*)g_xh;
    } else {
        src = w - nx4;
        dst = ((uint2*)g_wh) - nx4;
    }
    float4 v[4];
#pragma unroll
    for (int j = 0; j < 4; j++) v[j] = src[base + j * 256];
#pragma unroll
    for (int j = 0; j < 4; j++) {
        __half2 lo = __floats2half2_rn(v[j].x, v[j].y);
        __half2 hi = __floats2half2_rn(v[j].z, v[j].w);
        dst[base + j * 256] = make_uint2(*(uint32_t*)&lo, *(uint32_t*)&hi);
    }
}

// ------------------------- GEMM -------------------------
// BM=128, BN=64, BK=64, 4 stages, 2 CTAs/SM. 256 threads = 8 warps (4x2),
// warp tile 32x32. f16 accumulation within each k-tile, f32 across k-tiles.
#define ST_B_OFF    16384
#define STAGE_BYTES 24576
#define N_STAGES    4
#define GEMM_SMEM   (N_STAGES * STAGE_BYTES)   // 98304

__global__ void __launch_bounds__(256, 2) gemm_fp16_kernel(float* __restrict__ out) {
    extern __shared__ char smem[];
    const uint32_t sb = smem_u32(smem);
    const int tid    = threadIdx.x;
    const int lane   = tid & 31;
    const int wid    = tid >> 5;
    const int warp_m = wid >> 1;   // 0..3 -> m offset *32
    const int warp_n = wid & 1;    // 0..1 -> n offset *32
    const int cta_m  = blockIdx.y * 128;
    const int cta_n  = blockIdx.x * 64;

    auto load_st = [&](int kt, int s) {
        uint32_t st = sb + s * STAGE_BYTES;
        // A: 128 rows x 8 chunks of 16B = 1024 chunks, 4/thread
#pragma unroll
        for (int i = 0; i < 4; i++) {
            int ch = tid + i * 256;
            int r = ch >> 3, c = ch & 7;
            size_t g = (size_t)(cta_m + r) * DDIM + kt * 64 + c * 8;
            cpa16(st + r * 128 + ((c ^ (r & 7)) * 16), g_xh + g);
        }
        // B: 64 k-rows x 8 chunks of 16B = 512 chunks, 2/thread
#pragma unroll
        for (int i = 0; i < 2; i++) {
            int ch = tid + i * 256;
            int k = ch >> 3, c = ch & 7;
            size_t g = (size_t)(kt * 64 + k) * DDIM + cta_n + c * 8;
            cpa16(st + ST_B_OFF + k * 128 + ((c ^ (k & 7)) * 16), g_wh + g);
        }
    };

    float c[2][4][4];
#pragma unroll
    for (int i = 0; i < 2; i++)
#pragma unroll
        for (int j = 0; j < 4; j++)
#pragma unroll
            for (int q = 0; q < 4; q++) c[i][j][q] = 0.0f;

    load_st(0, 0); cp_commit();
    load_st(1, 1); cp_commit();
    load_st(2, 2); cp_commit();

    for (int kt = 0; kt < 16; kt++) {
        if (kt < 14)       cp_wait2();
        else if (kt == 14) cp_wait1();
        else               cp_wait0();
        __syncthreads();
        if (kt + 3 < 16) {
            load_st(kt + 3, (kt + 3) & 3);
            cp_commit();
        }

        uint32_t st = sb + (kt & 3) * STAGE_BYTES;

        // f16 partial accumulators for this k-tile (K=64)
        uint32_t c16[2][4][2];
#pragma unroll
        for (int i = 0; i < 2; i++)
#pragma unroll
            for (int j = 0; j < 4; j++) {
                c16[i][j][0] = 0u;
                c16[i][j][1] = 0u;
            }

#pragma unroll
        for (int kk = 0; kk < 4; kk++) {
            uint32_t a[2][4], b[2][4];
#pragma unroll
            for (int mt = 0; mt < 2; mt++) {
                int row = warp_m * 32 + mt * 16 + (lane & 15);
                int ch  = kk * 2 + (lane >> 4);
                ldsm4(a[mt], st + row * 128 + ((ch ^ (row & 7)) * 16));
            }
#pragma unroll
            for (int nt = 0; nt < 2; nt++) {
                int k  = kk * 16 + (lane & 15);
                int nc = warp_n * 4 + nt * 2 + (lane >> 4);
                ldsm4t(b[nt], st + ST_B_OFF + k * 128 + ((nc ^ (k & 7)) * 16));
            }
#pragma unroll
            for (int mt = 0; mt < 2; mt++)
#pragma unroll
                for (int nj = 0; nj < 4; nj++)
                    mma16816_f16(c16[mt][nj], a[mt], &b[nj >> 1][(nj & 1) * 2]);
        }

        // Flush f16 partials into f32 accumulators (fma/alu pipes, overlaps
        // other warps' tensor work).
#pragma unroll
        for (int mt = 0; mt < 2; mt++)
#pragma unroll
            for (int nj = 0; nj < 4; nj++) {
                float2 lo = __half22float2(*reinterpret_cast<__half2*>(&c16[mt][nj][0]));
                float2 hi = __half22float2(*reinterpret_cast<__half2*>(&c16[mt][nj][1]));
                c[mt][nj][0] += lo.x;
                c[mt][nj][1] += lo.y;
                c[mt][nj][2] += hi.x;
                c[mt][nj][3] += hi.y;
            }
    }

    // Epilogue: direct f32 stores from fragments
#pragma unroll
    for (int mt = 0; mt < 2; mt++) {
#pragma unroll
        for (int nj = 0; nj < 4; nj++) {
            int row = cta_m + warp_m * 32 + mt * 16 + (lane >> 2);
            int col = cta_n + warp_n * 32 + nj * 8 + (lane & 3) * 2;
            *reinterpret_cast<float2*>(&out[(size_t)row * DDIM + col]) =
                make_float2(c[mt][nj][0], c[mt][nj][1]);
            *reinterpret_cast<float2*>(&out[(size_t)(row + 8) * DDIM + col]) =
                make_float2(c[mt][nj][2], c[mt][nj][3]);
        }
    }
}

// ------------------------- launch -------------------------
extern "C" void kernel_launch(void* const* d_in, const int* in_sizes, int n_in,
                              void* d_out, int out_size) {
    const float* x = (const float*)d_in[0];                 // [8192,1024]
    const float* kern = (const float*)d_in[1];              // [3,1024,1024]
    const float* wv = kern + 2L * DDIM * DDIM;              // kernel[2]: [K,N]
    float* out = (float*)d_out;

    const int nx4 = BROWS * DDIM / 4;   // 2,097,152 (= 2048 blocks * 1024)
    const int nw4 = DDIM * DDIM / 4;    // 262,144   (= 256 blocks * 1024)
    cvt_kernel<<<(nx4 + nw4) / 1024, 256>>>((const float4*)x, (const float4*)wv, nx4);

    cudaFuncSetAttribute(gemm_fp16_kernel,
                         cudaFuncAttributeMaxDynamicSharedMemorySize, GEMM_SMEM);
    dim3 grid(DDIM / 64, BROWS / 128);  // (16, 64) = 1024 CTAs
    gemm_fp16_kernel<<<grid, 256, GEMM_SMEM>>>(out);
}

// round 9
// speedup vs baseline: 1.0739x; 1.0739x over previous
#include <cuda_runtime.h>
#include <cuda_fp16.h>
#include <cstdint>

// out = x @ kernel[2]  (seq_len==1 -> softmax over length-1 axis is identity)
// x: [8192,1024] f32, kernel: [3,1024,1024] f32, out: [8192,1024] f32
#define BROWS 8192
#define DDIM  1024

__device__ __half g_xh[BROWS * DDIM];   // 16 MB
__device__ __half g_wh[DDIM * DDIM];    // 2 MB, [K,N] row-major

// ------------------------- PTX helpers -------------------------
static __device__ __forceinline__ uint32_t smem_u32(const void* p) {
    uint32_t a;
    asm("{ .reg .u64 t; cvta.to.shared.u64 t, %1; cvt.u32.u64 %0, t; }" : "=r"(a) : "l"(p));
    return a;
}
static __device__ __forceinline__ void cpa16(uint32_t saddr, const void* gptr) {
    asm volatile("cp.async.cg.shared.global [%0], [%1], 16;" :: "r"(saddr), "l"(gptr));
}
static __device__ __forceinline__ void cp_commit() {
    asm volatile("cp.async.commit_group;" ::: "memory");
}
static __device__ __forceinline__ void cp_wait2() {
    asm volatile("cp.async.wait_group 2;" ::: "memory");
}
static __device__ __forceinline__ void cp_wait1() {
    asm volatile("cp.async.wait_group 1;" ::: "memory");
}
static __device__ __forceinline__ void cp_wait0() {
    asm volatile("cp.async.wait_group 0;" ::: "memory");
}
static __device__ __forceinline__ void ldsm4(uint32_t* r, uint32_t a) {
    asm volatile("ldmatrix.sync.aligned.m8n8.x4.shared.b16 {%0,%1,%2,%3}, [%4];"
                 : "=r"(r[0]), "=r"(r[1]), "=r"(r[2]), "=r"(r[3]) : "r"(a));
}
static __device__ __forceinline__ void ldsm4t(uint32_t* r, uint32_t a) {
    asm volatile("ldmatrix.sync.aligned.m8n8.x4.trans.shared.b16 {%0,%1,%2,%3}, [%4];"
                 : "=r"(r[0]), "=r"(r[1]), "=r"(r[2]), "=r"(r[3]) : "r"(a));
}
static __device__ __forceinline__ void mma16816(float* c, const uint32_t* a, const uint32_t* b) {
    asm volatile(
        "mma.sync.aligned.m16n8k16.row.col.f32.f16.f16.f32 "
        "{%0,%1,%2,%3}, {%4,%5,%6,%7}, {%8,%9}, {%0,%1,%2,%3};"
        : "+f"(c[0]), "+f"(c[1]), "+f"(c[2]), "+f"(c[3])
        : "r"(a[0]), "r"(a[1]), "r"(a[2]), "r"(a[3]), "r"(b[0]), "r"(b[1]));
}

// ------------------------- convert kernel -------------------------
// Blocks 0..2047 convert x, 2048..2303 convert w (nx4 = 2048*1024, exact split).
__global__ void __launch_bounds__(256) cvt_kernel(const float4* __restrict__ x,
                                                  const float4* __restrict__ w,
                                                  int nx4) {
    int base = blockIdx.x * 1024 + threadIdx.x;
    const float4* src;
    uint2* dst;
    if (base < nx4) {
        src = x;
        dst = (uint2*)g_xh;
    } else {
        src = w - nx4;
        dst = ((uint2*)g_wh) - nx4;
    }
    float4 v[4];
#pragma unroll
    for (int j = 0; j < 4; j++) v[j] = src[base + j * 256];
#pragma unroll
    for (int j = 0; j < 4; j++) {
        __half2 lo = __floats2half2_rn(v[j].x, v[j].y);
        __half2 hi = __floats2half2_rn(v[j].z, v[j].w);
        dst[base + j * 256] = make_uint2(*(uint32_t*)&lo, *(uint32_t*)&hi);
    }
}

// ------------------------- GEMM -------------------------
// BM=128, BN=64, BK=64, 4 stages, 2 CTAs/SM. 128 threads = 4 warps (2x2),
// warp tile 64x32 (A-fragment reuse: 192B smem traffic per HMMA).
// Stage: A 16KB [128 rows x 128B sw] | B 8KB [64 k-rows x 128B sw].
#define ST_B_OFF    16384
#define STAGE_BYTES 24576
#define N_STAGES    4
#define GEMM_SMEM   (N_STAGES * STAGE_BYTES)   // 98304

__global__ void __launch_bounds__(128, 2) gemm_fp16_kernel(float* __restrict__ out) {
    extern __shared__ char smem[];
    const uint32_t sb = smem_u32(smem);
    const int tid    = threadIdx.x;
    const int lane   = tid & 31;
    const int wid    = tid >> 5;
    const int warp_m = wid >> 1;   // 0..1 -> m offset *64
    const int warp_n = wid & 1;    // 0..1 -> n offset *32
    const int cta_m  = blockIdx.y * 128;
    const int cta_n  = blockIdx.x * 64;

    auto load_st = [&](int kt, int s) {
        uint32_t st = sb + s * STAGE_BYTES;
        // A: 128 rows x 8 chunks of 16B = 1024 chunks, 8/thread
#pragma unroll
        for (int i = 0; i < 8; i++) {
            int ch = tid + i * 128;
            int r = ch >> 3, c = ch & 7;
            size_t g = (size_t)(cta_m + r) * DDIM + kt * 64 + c * 8;
            cpa16(st + r * 128 + ((c ^ (r & 7)) * 16), g_xh + g);
        }
        // B: 64 k-rows x 8 chunks of 16B = 512 chunks, 4/thread
#pragma unroll
        for (int i = 0; i < 4; i++) {
            int ch = tid + i * 128;
            int k = ch >> 3, c = ch & 7;
            size_t g = (size_t)(kt * 64 + k) * DDIM + cta_n + c * 8;
            cpa16(st + ST_B_OFF + k * 128 + ((c ^ (k & 7)) * 16), g_wh + g);
        }
    };

    float c[4][4][4];
#pragma unroll
    for (int i = 0; i < 4; i++)
#pragma unroll
        for (int j = 0; j < 4; j++)
#pragma unroll
            for (int q = 0; q < 4; q++) c[i][j][q] = 0.0f;

    load_st(0, 0); cp_commit();
    load_st(1, 1); cp_commit();
    load_st(2, 2); cp_commit();

    for (int kt = 0; kt < 16; kt++) {
        if (kt < 14)       cp_wait2();
        else if (kt == 14) cp_wait1();
        else               cp_wait0();
        __syncthreads();
        if (kt + 3 < 16) {
            load_st(kt + 3, (kt + 3) & 3);
            cp_commit();
        }

        uint32_t st = sb + (kt & 3) * STAGE_BYTES;
#pragma unroll
        for (int kk = 0; kk < 4; kk++) {
            uint32_t a[4][4], b[2][4];
#pragma unroll
            for (int mt = 0; mt < 4; mt++) {
                int row = warp_m * 64 + mt * 16 + (lane & 15);
                int ch  = kk * 2 + (lane >> 4);
                ldsm4(a[mt], st + row * 128 + ((ch ^ (row & 7)) * 16));
            }
#pragma unroll
            for (int nt = 0; nt < 2; nt++) {
                int k  = kk * 16 + (lane & 15);
                int nc = warp_n * 4 + nt * 2 + (lane >> 4);
                ldsm4t(b[nt], st + ST_B_OFF + k * 128 + ((nc ^ (k & 7)) * 16));
            }
#pragma unroll
            for (int mt = 0; mt < 4; mt++)
#pragma unroll
                for (int nj = 0; nj < 4; nj++)
                    mma16816(c[mt][nj], a[mt], &b[nj >> 1][(nj & 1) * 2]);
        }
    }

    // Epilogue: direct f32 stores from fragments
#pragma unroll
    for (int mt = 0; mt < 4; mt++) {
#pragma unroll
        for (int nj = 0; nj < 4; nj++) {
            int row = cta_m + warp_m * 64 + mt * 16 + (lane >> 2);
            int col = cta_n + warp_n * 32 + nj * 8 + (lane & 3) * 2;
            *reinterpret_cast<float2*>(&out[(size_t)row * DDIM + col]) =
                make_float2(c[mt][nj][0], c[mt][nj][1]);
            *reinterpret_cast<float2*>(&out[(size_t)(row + 8) * DDIM + col]) =
                make_float2(c[mt][nj][2], c[mt][nj][3]);
        }
    }
}

// ------------------------- launch -------------------------
extern "C" void kernel_launch(void* const* d_in, const int* in_sizes, int n_in,
                              void* d_out, int out_size) {
    const float* x = (const float*)d_in[0];                 // [8192,1024]
    const float* kern = (const float*)d_in[1];              // [3,1024,1024]
    const float* wv = kern + 2L * DDIM * DDIM;              // kernel[2]: [K,N]
    float* out = (float*)d_out;

    const int nx4 = BROWS * DDIM / 4;   // 2,097,152 (= 2048 blocks * 1024)
    const int nw4 = DDIM * DDIM / 4;    // 262,144   (= 256 blocks * 1024)
    cvt_kernel<<<(nx4 + nw4) / 1024, 256>>>((const float4*)x, (const float4*)wv, nx4);

    cudaFuncSetAttribute(gemm_fp16_kernel,
                         cudaFuncAttributeMaxDynamicSharedMemorySize, GEMM_SMEM);
    dim3 grid(DDIM / 64, BROWS / 128);  // (16, 64) = 1024 CTAs
    gemm_fp16_kernel<<<grid, 128, GEMM_SMEM>>>(out);
}